// round 3
// baseline (speedup 1.0000x reference)
#include <cuda_runtime.h>
#include <math.h>

#define N_SAMP 1024
#define XD 768
#define LOWER 300
#define NJ 8          // number of j-splits in pair kernel
#define TI 32         // i tile (rows of hy)
#define TJ 128        // j tile (rows of hxb)
#define KC 60         // K chunk (300 = 5 * 60)

// scratch (static device arrays: no allocation allowed in kernel_launch)
__device__ float  g_hxbT[LOWER * N_SAMP];  // [k][j]  = (x @ Wx + b1)^T
__device__ float  g_hyT [LOWER * N_SAMP];  // [k][i]  = (y @ Wy)^T
__device__ float2 g_part[N_SAMP * NJ];     // per-row partial (max, sumexp)
__device__ float  g_T0  [N_SAMP];          // softplus(logit[i,i])

// ---------------------------------------------------------------------------
// GEMM: outT[c][n] = sum_d A[n][d] * W[d][c] (+ bias[c])
// z=0: A=x, W=W1[0:768],   bias=b1, out=g_hxbT
// z=1: A=y, W=W1[768:1536], no bias, out=g_hyT
// BM=64, BN=64, BK=16, 256 threads, 4x4 per thread
// ---------------------------------------------------------------------------
__global__ __launch_bounds__(256)
void gemm_kernel(const float* __restrict__ x,
                 const float* __restrict__ y,
                 const float* __restrict__ W1,
                 const float* __restrict__ b1) {
    const int BM = 64, BN = 64, BK = 16;
    __shared__ float As[BK][BM];   // [k][n]
    __shared__ float Bs[BK][BN];   // [k][c]

    int tx = threadIdx.x;          // 0..15 -> n dim
    int ty = threadIdx.y;          // 0..15 -> c dim
    int tid = ty * 16 + tx;

    int n0 = blockIdx.x * BM;
    int c0 = blockIdx.y * BN;

    const float* A;
    const float* W;
    float* outT;
    bool hasBias;
    if (blockIdx.z == 0) { A = x; W = W1;               hasBias = true;  outT = g_hxbT; }
    else                 { A = y; W = W1 + XD * LOWER;  hasBias = false; outT = g_hyT;  }

    float acc[4][4] = {};

    // A tile load mapping: 64 rows x 16 cols = 256 float4
    int a_row  = tid >> 2;            // 0..63
    int a_col4 = (tid & 3) * 4;       // 0,4,8,12
    // B tile load mapping: 16 rows x 64 cols = 256 float4
    int b_row  = tid >> 4;            // 0..15
    int b_col4 = (tid & 15) * 4;      // 0..60

    for (int k0 = 0; k0 < XD; k0 += BK) {
        float4 av = *(const float4*)&A[(n0 + a_row) * XD + k0 + a_col4];
        As[a_col4 + 0][a_row] = av.x;
        As[a_col4 + 1][a_row] = av.y;
        As[a_col4 + 2][a_row] = av.z;
        As[a_col4 + 3][a_row] = av.w;

        int gc = c0 + b_col4;
        float4 bv = make_float4(0.f, 0.f, 0.f, 0.f);
        if (gc < LOWER) bv = *(const float4*)&W[(k0 + b_row) * LOWER + gc];
        *(float4*)&Bs[b_row][b_col4] = bv;

        __syncthreads();
        #pragma unroll
        for (int k = 0; k < BK; k++) {
            float4 a = *(const float4*)&As[k][tx * 4];
            float4 b = *(const float4*)&Bs[k][ty * 4];
            float ar[4] = {a.x, a.y, a.z, a.w};
            float bc[4] = {b.x, b.y, b.z, b.w};
            #pragma unroll
            for (int r = 0; r < 4; r++)
                #pragma unroll
                for (int c = 0; c < 4; c++)
                    acc[r][c] = fmaf(ar[r], bc[c], acc[r][c]);
        }
        __syncthreads();
    }

    float bias[4];
    #pragma unroll
    for (int c = 0; c < 4; c++) {
        int gc = c0 + ty * 4 + c;
        bias[c] = (hasBias && gc < LOWER) ? b1[gc] : 0.f;
    }
    #pragma unroll
    for (int c = 0; c < 4; c++) {
        int gc = c0 + ty * 4 + c;
        if (gc < LOWER) {
            #pragma unroll
            for (int r = 0; r < 4; r++) {
                int gn = n0 + tx * 4 + r;
                outT[gc * N_SAMP + gn] = acc[r][c] + bias[c];
            }
        }
    }
}

// ---------------------------------------------------------------------------
// Pair kernel: block = (32 i-rows) x (128 j-cols), full K=300.
// logit[i,j] = sum_k relu(hy[i,k] + hxb[j,k]) * w2[k] + b2
// sp = softplus(logit); per-row partial (max, sum exp(sp-max)) over this
// block's 128 j's -> g_part. Diagonal sp -> g_T0.
// ---------------------------------------------------------------------------
__global__ __launch_bounds__(256)
void pair_kernel(const float* __restrict__ W2,
                 const float* __restrict__ b2p) {
    __shared__ float sHy[KC * TI];
    __shared__ float sHx[KC * TJ];
    __shared__ float sW[KC];

    int tid  = threadIdx.x;       // 0..255
    int warp = tid >> 5;          // 0..7  -> i sub-tile
    int lane = tid & 31;          // 0..31 -> j sub-tile
    int i0 = blockIdx.x * TI;
    int j0 = blockIdx.y * TJ;

    float acc[4][4] = {};

    for (int k0 = 0; k0 < LOWER; k0 += KC) {
        #pragma unroll
        for (int idx = tid; idx < KC * TI; idx += 256) {
            int kk = idx >> 5, ii = idx & 31;
            sHy[idx] = g_hyT[(k0 + kk) * N_SAMP + i0 + ii];
        }
        #pragma unroll
        for (int idx = tid; idx < KC * TJ; idx += 256) {
            int kk = idx >> 7, jj = idx & 127;
            sHx[idx] = g_hxbT[(k0 + kk) * N_SAMP + j0 + jj];
        }
        if (tid < KC) sW[tid] = W2[k0 + tid];
        __syncthreads();

        #pragma unroll 10
        for (int k = 0; k < KC; k++) {
            float4 a = ((const float4*)(sHy + k * TI))[warp];
            float4 b = ((const float4*)(sHx + k * TJ))[lane];
            float w = sW[k];
            float ar[4] = {a.x, a.y, a.z, a.w};
            float bc[4] = {b.x, b.y, b.z, b.w};
            #pragma unroll
            for (int r = 0; r < 4; r++) {
                #pragma unroll
                for (int c = 0; c < 4; c++) {
                    float t = ar[r] + bc[c];
                    t = fmaxf(t, 0.f);
                    acc[r][c] = fmaf(t, w, acc[r][c]);
                }
            }
        }
        __syncthreads();
    }

    float b2 = *b2p;
    #pragma unroll
    for (int r = 0; r < 4; r++) {
        int gi = i0 + warp * 4 + r;
        float sp[4];
        float m = -1e30f;
        #pragma unroll
        for (int c = 0; c < 4; c++) {
            float l = acc[r][c] + b2;
            float s = fmaxf(l, 0.f) + log1pf(expf(-fabsf(l)));
            sp[c] = s;
            int gj = j0 + lane * 4 + c;
            if (gj == gi) g_T0[gi] = s;
            m = fmaxf(m, s);
        }
        #pragma unroll
        for (int o = 16; o; o >>= 1)
            m = fmaxf(m, __shfl_xor_sync(0xffffffffu, m, o));
        float ssum = 0.f;
        #pragma unroll
        for (int c = 0; c < 4; c++) ssum += expf(sp[c] - m);
        #pragma unroll
        for (int o = 16; o; o >>= 1)
            ssum += __shfl_xor_sync(0xffffffffu, ssum, o);
        if (lane == 0) g_part[gi * NJ + blockIdx.y] = make_float2(m, ssum);
    }
}

// ---------------------------------------------------------------------------
// Finalize: combine NJ partials per row -> logsumexp; reduce T0 and lse means.
// ---------------------------------------------------------------------------
__global__ __launch_bounds__(1024)
void finalize_kernel(float* __restrict__ out) {
    int i = threadIdx.x;  // 1024 threads
    float M = -1e30f;
    float2 p[NJ];
    #pragma unroll
    for (int j = 0; j < NJ; j++) {
        p[j] = g_part[i * NJ + j];
        M = fmaxf(M, p[j].x);
    }
    float S = 0.f;
    #pragma unroll
    for (int j = 0; j < NJ; j++) S += p[j].y * expf(p[j].x - M);
    float lse = M + logf(S);
    float t0  = g_T0[i];

    __shared__ float sA[1024];
    __shared__ float sB[1024];
    sA[i] = t0;
    sB[i] = lse;
    __syncthreads();
    for (int s = 512; s; s >>= 1) {
        if (i < s) { sA[i] += sA[i + s]; sB[i] += sB[i + s]; }
        __syncthreads();
    }
    if (i == 0)
        out[0] = sA[0] / (float)N_SAMP - sB[0] / (float)N_SAMP - logf((float)N_SAMP);
}

extern "C" void kernel_launch(void* const* d_in, const int* in_sizes, int n_in,
                              void* d_out, int out_size) {
    const float* x  = (const float*)d_in[0];
    const float* y  = (const float*)d_in[1];
    const float* W1 = (const float*)d_in[2];
    const float* b1 = (const float*)d_in[3];
    const float* W2 = (const float*)d_in[4];
    const float* b2 = (const float*)d_in[5];
    float* out = (float*)d_out;

    gemm_kernel<<<dim3(16, 5, 2), dim3(16, 16)>>>(x, y, W1, b1);
    pair_kernel<<<dim3(32, 8), 256>>>(W2, b2);
    finalize_kernel<<<1, 1024>>>(out);
}